// round 14
// baseline (speedup 1.0000x reference)
#include <cuda_runtime.h>
#include <cuda_fp16.h>
#include <math.h>
#include <stdint.h>

#define NE   64
#define TK   8
#define DIM  2048
#define TM   128            // tokens per CTA
#define KC   128            // fp32 k per chunk (128 fp16 = 256B row)
#define NCH  (DIM / KC)     // 16 chunks
#define NTH  256
#define INV2048 (1.0f / 2048.0f)
#define LS_STRIDE 68

// stage byte layout: 256B rows, XOR-swizzled 16B chunks within 128B halves
#define AH_B 0
#define AL_B 32768
#define BH_B 65536
#define BL_B 81920
#define STG_B 98304
#define DYN_BYTES (2 * STG_B)    // 196608

__device__ __align__(16) uint16_t g_wh16[NE * DIM];   // W hi (fp16)
__device__ __align__(16) uint16_t g_wl16[NE * DIM];   // W lo (fp16, scaled 2^11)
__device__ __align__(16) float g_bias[NE];
__device__ float g_nbs;
__device__ float g_acc[NE];
__device__ unsigned int g_done;   // zero-init; reset by last CTA each run

// swizzled byte offset of 16B chunk (row, c 0..15) within a plane (256B rows)
#define SWZ256(row, c) (((row) << 8) + (((c) & 8) << 4) + (((((c) & 7) ^ ((row) & 7))) << 4))

// 2-term fp16 split of (x,y) -> packed hi fp16x2, lo fp16x2 (lo scaled 2^11)
static __device__ __forceinline__ void split2(float x, float y,
                                              uint32_t& hh, uint32_t& ll)
{
    __half2 a = __floats2half2_rn(x, y);
    float rx = (x - __half2float(__low2half(a))) * 2048.f;
    float ry = (y - __half2float(__high2half(a))) * 2048.f;
    __half2 l = __floats2half2_rn(rx, ry);
    hh = *(uint32_t*)&a;
    ll = *(uint32_t*)&l;
}

static __device__ __forceinline__ void mma16f(float* c,
    uint32_t a0, uint32_t a1, uint32_t a2, uint32_t a3, uint32_t b0, uint32_t b1)
{
    asm volatile(
        "mma.sync.aligned.m16n8k16.row.col.f32.f16.f16.f32 "
        "{%0,%1,%2,%3}, {%4,%5,%6,%7}, {%8,%9}, {%0,%1,%2,%3};"
        : "+f"(c[0]), "+f"(c[1]), "+f"(c[2]), "+f"(c[3])
        : "r"(a0), "r"(a1), "r"(a2), "r"(a3), "r"(b0), "r"(b1));
}

static __device__ __forceinline__ void ldsm4(uint32_t& r0, uint32_t& r1,
                                             uint32_t& r2, uint32_t& r3, uint32_t a)
{
    asm volatile("ldmatrix.sync.aligned.m8n8.x4.shared.b16 {%0,%1,%2,%3}, [%4];"
                 : "=r"(r0), "=r"(r1), "=r"(r2), "=r"(r3) : "r"(a));
}

static __device__ __forceinline__ void cpa16(uint32_t dst, const void* src) {
    asm volatile("cp.async.ca.shared.global [%0], [%1], 16;"
                 :: "r"(dst), "l"(src) : "memory");
}

// ---------------------------------------------------------------------------
// Setup: split W into fp16 hi/lo planes (blocks 0..63), bias (block 64)
// ---------------------------------------------------------------------------
__global__ void k_setup(const float* __restrict__ W,
                        const float* __restrict__ loads,
                        const float* __restrict__ bs)
{
    int b = blockIdx.x, tid = threadIdx.x;

    if (b < NE) {
        const float2* wr = (const float2*)(W + (size_t)b * DIM);
        uint32_t* wh = (uint32_t*)g_wh16;
        uint32_t* wl = (uint32_t*)g_wl16;
        #pragma unroll
        for (int u = 0; u < 4; u++) {
            int f = u * 256 + tid;
            float2 v = wr[f];
            uint32_t hh, ll;
            split2(v.x, v.y, hh, ll);
            int idx = b * (DIM / 2) + f;
            wh[idx] = hh;
            wl[idx] = ll;
        }
    } else {
        __shared__ float s[NE], s2[NE];
        if (tid < NE) s[tid] = loads[tid];
        __syncthreads();
        float sum = 0.f, q = 0.f;
        const float t = 1.0f / (float)NE;
        if (tid < NE) {
            #pragma unroll
            for (int i = 0; i < NE; i++) sum += s[i];
            sum = fmaxf(sum, 1e-8f);
            q = s[tid] / sum;
            s2[tid] = t * (logf(t) - logf(fmaxf(q, 1e-8f)));
        }
        __syncthreads();
        if (tid < NE) {
            float kl = 0.f;
            #pragma unroll
            for (int i = 0; i < NE; i++) kl += s2[i];
            float adaptive = 1.0f / (1.0f + expf(-10.0f * kl));
            float nbs = 0.9f * bs[0] + 0.1f * adaptive;
            g_bias[tid] = tanhf((q - t) * (float)NE) * nbs;
            g_acc[tid] = 0.f;
            if (tid == 0) g_nbs = nbs;
        }
    }
}

// ---------------------------------------------------------------------------
// Router: fp16 2-term / 3-product mma16 GEMM, KC=128, 8 warps, 16 barriers
// warp w (0..7): h = w&1 token half, e2 = (w>>1)&1 expert half, ksw = w>>2
// Each warp: 4 k16-steps per chunk; X fill sub-batched between MMA blocks.
// ---------------------------------------------------------------------------
__global__ __launch_bounds__(NTH, 1) void k_router(
    const float* __restrict__ X,      // [ntok, DIM]
    const float* __restrict__ noise,  // [ntok, NE]
    const float* __restrict__ loads,  // [NE]
    float* __restrict__ out,
    int ntok)
{
    extern __shared__ __align__(16) char dsm[];
    __shared__ float sLoads[NE];
    __shared__ float sBias[NE];
    __shared__ int sLast;

    const int tid  = threadIdx.x;
    const int lane = tid & 31;
    const int warp = tid >> 5;
    const int h    = warp & 1;
    const int e2   = (warp >> 1) & 1;
    const int ksw  = warp >> 2;
    const int g    = lane >> 2;
    const int tig  = lane & 3;
    const int t0   = blockIdx.x * TM;

    if (tid < NE) { sLoads[tid] = 0.f; sBias[tid] = g_bias[tid]; }

    const uint32_t smem32 = (uint32_t)__cvta_generic_to_shared(dsm);

    // ldsm lane decomposition
    const int laneA15 = lane & 15;
    const int kaSel = lane >> 4;           // A chunk select within k16
    const int kbSel = (lane >> 3) & 1;     // B chunk select
    const int rowBbase = 32 * e2 + ((lane >> 4) << 3) + (lane & 7);

    float acc0[4][4][4], accS[4][4][4];
    #pragma unroll
    for (int i = 0; i < 4; i++)
        #pragma unroll
        for (int j = 0; j < 4; j++)
            #pragma unroll
            for (int q = 0; q < 4; q++) { acc0[i][j][q] = 0.f; accS[i][j][q] = 0.f; }

    // X fill mapping: flat float4 f = u*256+tid -> row = u*8 + warp, col4 = lane
    // u 0..15 total per chunk; processed in 4 batches of 4.

    // ---- prologue: fill chunk 0 into stage 0 ----
    {
        #pragma unroll
        for (int u = 0; u < 16; u++) {
            int row = u * 8 + warp;
            float4 v = *(const float4*)(X + (size_t)(t0 + row) * DIM + lane * 4);
            uint32_t h0, l0, h1, l1;
            split2(v.x, v.y, h0, l0);
            split2(v.z, v.w, h1, l1);
            uint32_t byte = (uint32_t)(SWZ256(row, (lane >> 1)) + (lane & 1) * 8);
            *(uint2*)(dsm + AH_B + byte) = make_uint2(h0, h1);
            *(uint2*)(dsm + AL_B + byte) = make_uint2(l0, l1);
        }
        #pragma unroll
        for (int u = 0; u < 4; u++) {
            int f = u * 256 + tid;
            int row = f >> 4, cc = f & 15;
            uint32_t dst = smem32 + (uint32_t)SWZ256(row, cc);
            cpa16(dst + BH_B, g_wh16 + (size_t)row * DIM + cc * 8);
            cpa16(dst + BL_B, g_wl16 + (size_t)row * DIM + cc * 8);
        }
        asm volatile("cp.async.commit_group;" ::: "memory");
        asm volatile("cp.async.wait_group 0;" ::: "memory");
    }
    __syncthreads();

    // ---- mainloop ----
    for (int c = 0; c < NCH; ++c) {
        const bool more = (c + 1 < NCH);
        const int kb = (c + 1) * KC;
        char* sd = dsm + ((c + 1) & 1) * STG_B;
        const uint32_t stg32 = smem32 + (uint32_t)((c & 1) * STG_B);

        // issue next B cp.async early
        if (more) {
            uint32_t sb = smem32 + (uint32_t)(((c + 1) & 1) * STG_B);
            #pragma unroll
            for (int u = 0; u < 4; u++) {
                int f = u * 256 + tid;
                int row = f >> 4, cc = f & 15;
                uint32_t dst = sb + (uint32_t)SWZ256(row, cc);
                cpa16(dst + BH_B, g_wh16 + (size_t)row * DIM + kb + cc * 8);
                cpa16(dst + BL_B, g_wl16 + (size_t)row * DIM + kb + cc * 8);
            }
            asm volatile("cp.async.commit_group;" ::: "memory");
        }

        float4 xr[4];
        // prefetch X batch 0 for c+1
        if (more) {
            #pragma unroll
            for (int s = 0; s < 4; s++) {
                int row = s * 8 + warp;
                xr[s] = *(const float4*)(X + (size_t)(t0 + row) * DIM + kb + lane * 4);
            }
        }

        #pragma unroll
        for (int kk = 0; kk < 4; kk++) {
            // ---- consume k16-step s = ksw*4 + kk ----
            const int s = ksw * 4 + kk;

            uint32_t Ah[4][4], Al[4][4];
            #pragma unroll
            for (int i = 0; i < 4; i++) {
                int rowA = 64 * h + 16 * i + laneA15;
                int kc = 2 * s + kaSel;
                uint32_t a = stg32 + (uint32_t)SWZ256(rowA, kc);
                ldsm4(Ah[i][0], Ah[i][1], Ah[i][2], Ah[i][3], a + AH_B);
                ldsm4(Al[i][0], Al[i][1], Al[i][2], Al[i][3], a + AL_B);
            }
            #pragma unroll
            for (int jp = 0; jp < 2; jp++) {
                int rowBj = rowBbase + 16 * jp;
                int kc = 2 * s + kbSel;
                uint32_t b = stg32 + (uint32_t)SWZ256(rowBj, kc);
                uint32_t Bh0, Bh1, Bh2, Bh3, Bl0, Bl1, Bl2, Bl3;
                ldsm4(Bh0, Bh1, Bh2, Bh3, b + BH_B);
                ldsm4(Bl0, Bl1, Bl2, Bl3, b + BL_B);
                #pragma unroll
                for (int i = 0; i < 4; i++) {
                    mma16f(acc0[i][2*jp],   Ah[i][0], Ah[i][1], Ah[i][2], Ah[i][3], Bh0, Bh1);
                    mma16f(accS[i][2*jp],   Ah[i][0], Ah[i][1], Ah[i][2], Ah[i][3], Bl0, Bl1);
                    mma16f(accS[i][2*jp],   Al[i][0], Al[i][1], Al[i][2], Al[i][3], Bh0, Bh1);
                    mma16f(acc0[i][2*jp+1], Ah[i][0], Ah[i][1], Ah[i][2], Ah[i][3], Bh2, Bh3);
                    mma16f(accS[i][2*jp+1], Ah[i][0], Ah[i][1], Ah[i][2], Ah[i][3], Bl2, Bl3);
                    mma16f(accS[i][2*jp+1], Al[i][0], Al[i][1], Al[i][2], Al[i][3], Bh2, Bh3);
                }
            }

            // ---- fill pipeline: STS batch kk, LDG batch kk+1 ----
            if (more) {
                #pragma unroll
                for (int s2 = 0; s2 < 4; s2++) {
                    int u = kk * 4 + s2;
                    int row = u * 8 + warp;
                    uint32_t h0, l0, h1, l1;
                    split2(xr[s2].x, xr[s2].y, h0, l0);
                    split2(xr[s2].z, xr[s2].w, h1, l1);
                    uint32_t byte = (uint32_t)(SWZ256(row, (lane >> 1)) + (lane & 1) * 8);
                    *(uint2*)(sd + AH_B + byte) = make_uint2(h0, h1);
                    *(uint2*)(sd + AL_B + byte) = make_uint2(l0, l1);
                }
                if (kk < 3) {
                    #pragma unroll
                    for (int s2 = 0; s2 < 4; s2++) {
                        int u = (kk + 1) * 4 + s2;
                        int row = u * 8 + warp;
                        xr[s2] = *(const float4*)(X + (size_t)(t0 + row) * DIM + kb + lane * 4);
                    }
                }
            }
        }

        if (more) asm volatile("cp.async.wait_group 0;" ::: "memory");
        __syncthreads();
    }

    // ---- cross-kstep reduction into logits tile Ls[128][68] ----
    float* Ls = (float*)dsm;
    for (int idx = tid; idx < TM * LS_STRIDE; idx += NTH) Ls[idx] = 0.f;
    __syncthreads();

    for (int round = 0; round < 2; round++) {
        if (ksw == round) {
            #pragma unroll
            for (int i = 0; i < 4; i++) {
                int rt = 64 * h + 16 * i + g;
                #pragma unroll
                for (int j = 0; j < 4; j++) {
                    int cc = 32 * e2 + 8 * j + 2 * tig;
                    Ls[rt * LS_STRIDE + cc]           += acc0[i][j][0] + accS[i][j][0] * INV2048;
                    Ls[rt * LS_STRIDE + cc + 1]       += acc0[i][j][1] + accS[i][j][1] * INV2048;
                    Ls[(rt + 8) * LS_STRIDE + cc]     += acc0[i][j][2] + accS[i][j][2] * INV2048;
                    Ls[(rt + 8) * LS_STRIDE + cc + 1] += acc0[i][j][3] + accS[i][j][3] * INV2048;
                }
            }
        }
        __syncthreads();
    }

    // ---- epilogue: per-token top-8 + softmax + load scatter ----
    if (tid < TM) {
        const int t = tid;
        size_t gt = (size_t)(t0 + t);

        float nzf[NE];
        const float4* nr = (const float4*)(noise + gt * NE);
        #pragma unroll
        for (int i = 0; i < 16; i++) {
            float4 v = nr[i];
            nzf[4 * i + 0] = v.x; nzf[4 * i + 1] = v.y;
            nzf[4 * i + 2] = v.z; nzf[4 * i + 3] = v.w;
        }

        float tv[TK];
        int   ti_[TK];
        #pragma unroll
        for (int k = 0; k < TK; k++) { tv[k] = -INFINITY; ti_[k] = -1; }

        for (int e = 0; e < NE; e++) {
            float v = Ls[t * LS_STRIDE + e] + 0.01f * nzf[e] - sBias[e];
            if (v > tv[TK - 1]) {                 // strict >: earlier equal value stays
                int p = TK - 1;
                while (p > 0 && tv[p - 1] < v) {  // stop at equal -> stable insert
                    tv[p] = tv[p - 1];
                    ti_[p] = ti_[p - 1];
                    --p;
                }
                tv[p] = v;
                ti_[p] = e;
            }
        }

        float m = tv[0];
        float w[TK];
        float ssum = 0.f;
        #pragma unroll
        for (int k = 0; k < TK; k++) { w[k] = expf(tv[k] - m); ssum += w[k]; }
        float inv = 1.0f / ssum;

        size_t woff = (size_t)ntok * TK;
        #pragma unroll
        for (int k = 0; k < TK; k++) {
            float wk = w[k] * inv;
            out[gt * TK + k]        = (float)ti_[k];
            out[woff + gt * TK + k] = wk;
            atomicAdd(&sLoads[ti_[k]], wk);
        }
    }
    __syncthreads();
    if (tid < NE) atomicAdd(&g_acc[tid], sLoads[tid]);

    // ---- fused finalize: last CTA writes EMA + bias strength ----
    __threadfence();
    __syncthreads();
    if (tid == 0) {
        unsigned int n = atomicAdd(&g_done, 1u);
        sLast = (n == gridDim.x - 1) ? 1 : 0;
    }
    __syncthreads();
    if (sLast && tid < NE) {
        float batch = atomicAdd(&g_acc[tid], 0.0f) / (float)ntok;
        size_t bofs = (size_t)ntok * TK * 2;
        out[bofs + tid] = 0.999f * loads[tid] + (1.0f - 0.999f) * batch;
        if (tid == 0) { out[bofs + NE] = g_nbs; g_done = 0u; }
    }
}

// ---------------------------------------------------------------------------
// Launch
// ---------------------------------------------------------------------------
extern "C" void kernel_launch(void* const* d_in, const int* in_sizes, int n_in,
                              void* d_out, int out_size)
{
    const float* X     = (const float*)d_in[0];  // hidden_states [4,4096,2048]
    const float* W     = (const float*)d_in[1];  // router_w [64,2048]
    const float* loads = (const float*)d_in[2];  // expert_loads [64]
    const float* bs    = (const float*)d_in[3];  // bias_strength [1]
    const float* noise = (const float*)d_in[4];  // noise [16384,64]
    float* out = (float*)d_out;

    int ntok = in_sizes[0] / DIM;

    cudaFuncSetAttribute(k_router, cudaFuncAttributeMaxDynamicSharedMemorySize, DYN_BYTES);

    k_setup<<<NE + 1, 256>>>(W, loads, bs);
    k_router<<<ntok / TM, NTH, DYN_BYTES>>>(X, noise, loads, out, ntok);
}

// round 15
// speedup vs baseline: 1.4331x; 1.4331x over previous
#include <cuda_runtime.h>
#include <cuda_fp16.h>
#include <math.h>
#include <stdint.h>

#define NE   64
#define TK   8
#define DIM  2048
#define TM   128            // tokens per CTA
#define KC   128            // fp32 k per chunk (128 fp16 = 256B row)
#define NCH  (DIM / KC)     // 16 chunks
#define NTH  512
#define INV32 (1.0f / 32.0f)
#define LS_STRIDE 68

// stage byte layout: 256B rows, XOR-swizzled 16B chunks within 128B halves
#define AH_B 0
#define AL_B 32768
#define BH_B 65536
#define BL_B 81920
#define STG_B 98304
#define DYN_BYTES (2 * STG_B)    // 196608

__device__ __align__(16) uint16_t g_wh16[NE * DIM];   // 32*W hi (fp16)
__device__ __align__(16) uint16_t g_wl16[NE * DIM];   // 32*W lo (fp16, unscaled residual)
__device__ __align__(16) float g_bias[NE];
__device__ float g_nbs;
__device__ float g_acc[NE];
__device__ unsigned int g_done;   // zero-init; reset by last CTA each run

// swizzled byte offset of 16B chunk (row, c 0..15) within a plane (256B rows)
#define SWZ256(row, c) (((row) << 8) + (((c) & 8) << 4) + (((((c) & 7) ^ ((row) & 7))) << 4))

// natural 2-term fp16 split of (x,y): hi = fp16(x), lo = fp16(x - hi)  (NO scaling)
static __device__ __forceinline__ void split2n(float x, float y,
                                               uint32_t& hh, uint32_t& ll)
{
    __half2 a = __floats2half2_rn(x, y);
    float rx = x - __half2float(__low2half(a));
    float ry = y - __half2float(__high2half(a));
    __half2 l = __floats2half2_rn(rx, ry);
    hh = *(uint32_t*)&a;
    ll = *(uint32_t*)&l;
}

static __device__ __forceinline__ void mma16f(float* c,
    uint32_t a0, uint32_t a1, uint32_t a2, uint32_t a3, uint32_t b0, uint32_t b1)
{
    asm volatile(
        "mma.sync.aligned.m16n8k16.row.col.f32.f16.f16.f32 "
        "{%0,%1,%2,%3}, {%4,%5,%6,%7}, {%8,%9}, {%0,%1,%2,%3};"
        : "+f"(c[0]), "+f"(c[1]), "+f"(c[2]), "+f"(c[3])
        : "r"(a0), "r"(a1), "r"(a2), "r"(a3), "r"(b0), "r"(b1));
}

static __device__ __forceinline__ void ldsm4(uint32_t& r0, uint32_t& r1,
                                             uint32_t& r2, uint32_t& r3, uint32_t a)
{
    asm volatile("ldmatrix.sync.aligned.m8n8.x4.shared.b16 {%0,%1,%2,%3}, [%4];"
                 : "=r"(r0), "=r"(r1), "=r"(r2), "=r"(r3) : "r"(a));
}

static __device__ __forceinline__ void cpa16(uint32_t dst, const void* src) {
    asm volatile("cp.async.ca.shared.global [%0], [%1], 16;"
                 :: "r"(dst), "l"(src) : "memory");
}

// ---------------------------------------------------------------------------
// Setup: split 32*W into fp16 hi/lo planes (blocks 0..63), bias (block 64)
// ---------------------------------------------------------------------------
__global__ void k_setup(const float* __restrict__ W,
                        const float* __restrict__ loads,
                        const float* __restrict__ bs)
{
    int b = blockIdx.x, tid = threadIdx.x;

    if (b < NE) {
        const float2* wr = (const float2*)(W + (size_t)b * DIM);
        uint32_t* wh = (uint32_t*)g_wh16;
        uint32_t* wl = (uint32_t*)g_wl16;
        #pragma unroll
        for (int u = 0; u < 4; u++) {
            int f = u * 256 + tid;
            float2 v = wr[f];
            uint32_t hh, ll;
            split2n(v.x * 32.f, v.y * 32.f, hh, ll);
            int idx = b * (DIM / 2) + f;
            wh[idx] = hh;
            wl[idx] = ll;
        }
    } else {
        __shared__ float s[NE], s2[NE];
        if (tid < NE) s[tid] = loads[tid];
        __syncthreads();
        float sum = 0.f, q = 0.f;
        const float t = 1.0f / (float)NE;
        if (tid < NE) {
            #pragma unroll
            for (int i = 0; i < NE; i++) sum += s[i];
            sum = fmaxf(sum, 1e-8f);
            q = s[tid] / sum;
            s2[tid] = t * (logf(t) - logf(fmaxf(q, 1e-8f)));
        }
        __syncthreads();
        if (tid < NE) {
            float kl = 0.f;
            #pragma unroll
            for (int i = 0; i < NE; i++) kl += s2[i];
            float adaptive = 1.0f / (1.0f + expf(-10.0f * kl));
            float nbs = 0.9f * bs[0] + 0.1f * adaptive;
            g_bias[tid] = tanhf((q - t) * (float)NE) * nbs;
            g_acc[tid] = 0.f;
            if (tid == 0) g_nbs = nbs;
        }
    }
}

// ---------------------------------------------------------------------------
// Router: fp16 single-acc 3-product mma16 GEMM, KC=128, 16 warps, 16 barriers
// warp w (0..15): h2 = w&3 token quarter, e2 = (w>>2)&1 expert half, ksw = w>>3
// ---------------------------------------------------------------------------
__global__ __launch_bounds__(NTH, 1) void k_router(
    const float* __restrict__ X,      // [ntok, DIM]
    const float* __restrict__ noise,  // [ntok, NE]
    const float* __restrict__ loads,  // [NE]
    float* __restrict__ out,
    int ntok)
{
    extern __shared__ __align__(16) char dsm[];
    __shared__ float sLoads[NE];
    __shared__ float sBias[NE];
    __shared__ int sLast;

    const int tid  = threadIdx.x;
    const int lane = tid & 31;
    const int warp = tid >> 5;
    const int h2   = warp & 3;        // token quarter (32 tokens)
    const int e2   = (warp >> 2) & 1; // expert half
    const int ksw  = warp >> 3;       // k64 half of chunk (4 k16-steps)
    const int g    = lane >> 2;
    const int tig  = lane & 3;
    const int t0   = blockIdx.x * TM;

    if (tid < NE) { sLoads[tid] = 0.f; sBias[tid] = g_bias[tid]; }

    const uint32_t smem32 = (uint32_t)__cvta_generic_to_shared(dsm);

    // ldsm lane decomposition
    const int laneA15 = lane & 15;
    const int kaSel = lane >> 4;           // A chunk select within k16
    const int kbSel = (lane >> 3) & 1;     // B chunk select
    const int rowBbase = 32 * e2 + ((lane >> 4) << 3) + (lane & 7);

    // X fill: flat float4 f = u*512+tid -> row = u*16 + warp, col4 = lane
    // B fill: f = u*512+tid -> row = f>>4, chunk = f&15  (u<2)

    float acc[2][4][4];
    #pragma unroll
    for (int i = 0; i < 2; i++)
        #pragma unroll
        for (int j = 0; j < 4; j++)
            #pragma unroll
            for (int q = 0; q < 4; q++) acc[i][j][q] = 0.f;

    float4 xr[8];

    // ---- prologue: fill chunk 0 into stage 0 ----
    {
        #pragma unroll
        for (int u = 0; u < 8; u++) {
            int row = u * 16 + warp;
            xr[u] = *(const float4*)(X + (size_t)(t0 + row) * DIM + lane * 4);
        }
        #pragma unroll
        for (int u = 0; u < 8; u++) {
            int row = u * 16 + warp;
            uint32_t h0, l0, h1, l1;
            split2n(xr[u].x, xr[u].y, h0, l0);
            split2n(xr[u].z, xr[u].w, h1, l1);
            uint32_t byte = (uint32_t)(SWZ256(row, (lane >> 1)) + (lane & 1) * 8);
            *(uint2*)(dsm + AH_B + byte) = make_uint2(h0, h1);
            *(uint2*)(dsm + AL_B + byte) = make_uint2(l0, l1);
        }
        #pragma unroll
        for (int u = 0; u < 2; u++) {
            int f = u * 512 + tid;
            int row = f >> 4, cc = f & 15;
            uint32_t dst = smem32 + (uint32_t)SWZ256(row, cc);
            cpa16(dst + BH_B, g_wh16 + (size_t)row * DIM + cc * 8);
            cpa16(dst + BL_B, g_wl16 + (size_t)row * DIM + cc * 8);
        }
        asm volatile("cp.async.commit_group;" ::: "memory");
        asm volatile("cp.async.wait_group 0;" ::: "memory");
    }
    __syncthreads();

    // ---- mainloop ----
    for (int c = 0; c < NCH; ++c) {
        const bool more = (c + 1 < NCH);
        const int kb = (c + 1) * KC;
        const uint32_t stg32 = smem32 + (uint32_t)((c & 1) * STG_B);

        if (more) {
            // next X to regs, next B via cp.async (consumed after this chunk)
            #pragma unroll
            for (int u = 0; u < 8; u++) {
                int row = u * 16 + warp;
                xr[u] = *(const float4*)(X + (size_t)(t0 + row) * DIM + kb + lane * 4);
            }
            uint32_t sb = smem32 + (uint32_t)(((c + 1) & 1) * STG_B);
            #pragma unroll
            for (int u = 0; u < 2; u++) {
                int f = u * 512 + tid;
                int row = f >> 4, cc = f & 15;
                uint32_t dst = sb + (uint32_t)SWZ256(row, cc);
                cpa16(dst + BH_B, g_wh16 + (size_t)row * DIM + kb + cc * 8);
                cpa16(dst + BL_B, g_wl16 + (size_t)row * DIM + kb + cc * 8);
            }
            asm volatile("cp.async.commit_group;" ::: "memory");
        }

        // ---- consume: 4 k16-steps, 3 product passes each (RAW distance 8) ----
        #pragma unroll
        for (int kk = 0; kk < 4; kk++) {
            const int s = ksw * 4 + kk;

            uint32_t Ah[2][4], Al[2][4], Bh[2][4], Bl[2][4];
            #pragma unroll
            for (int i = 0; i < 2; i++) {
                int rowA = 32 * h2 + 16 * i + laneA15;
                int kc = 2 * s + kaSel;
                uint32_t a = stg32 + (uint32_t)SWZ256(rowA, kc);
                ldsm4(Ah[i][0], Ah[i][1], Ah[i][2], Ah[i][3], a + AH_B);
                ldsm4(Al[i][0], Al[i][1], Al[i][2], Al[i][3], a + AL_B);
            }
            #pragma unroll
            for (int jp = 0; jp < 2; jp++) {
                int rowBj = rowBbase + 16 * jp;
                int kc = 2 * s + kbSel;
                uint32_t b = stg32 + (uint32_t)SWZ256(rowBj, kc);
                ldsm4(Bh[jp][0], Bh[jp][1], Bh[jp][2], Bh[jp][3], b + BH_B);
                ldsm4(Bl[jp][0], Bl[jp][1], Bl[jp][2], Bl[jp][3], b + BL_B);
            }

            // pass 1: hi*hi
            #pragma unroll
            for (int i = 0; i < 2; i++)
                #pragma unroll
                for (int jp = 0; jp < 2; jp++) {
                    mma16f(acc[i][2*jp],   Ah[i][0], Ah[i][1], Ah[i][2], Ah[i][3], Bh[jp][0], Bh[jp][1]);
                    mma16f(acc[i][2*jp+1], Ah[i][0], Ah[i][1], Ah[i][2], Ah[i][3], Bh[jp][2], Bh[jp][3]);
                }
            // pass 2: hi*lo
            #pragma unroll
            for (int i = 0; i < 2; i++)
                #pragma unroll
                for (int jp = 0; jp < 2; jp++) {
                    mma16f(acc[i][2*jp],   Ah[i][0], Ah[i][1], Ah[i][2], Ah[i][3], Bl[jp][0], Bl[jp][1]);
                    mma16f(acc[i][2*jp+1], Ah[i][0], Ah[i][1], Ah[i][2], Ah[i][3], Bl[jp][2], Bl[jp][3]);
                }
            // pass 3: lo*hi
            #pragma unroll
            for (int i = 0; i < 2; i++)
                #pragma unroll
                for (int jp = 0; jp < 2; jp++) {
                    mma16f(acc[i][2*jp],   Al[i][0], Al[i][1], Al[i][2], Al[i][3], Bh[jp][0], Bh[jp][1]);
                    mma16f(acc[i][2*jp+1], Al[i][0], Al[i][1], Al[i][2], Al[i][3], Bh[jp][2], Bh[jp][3]);
                }
        }

        // ---- store next X + drain B cp.async ----
        if (more) {
            char* sd = dsm + ((c + 1) & 1) * STG_B;
            #pragma unroll
            for (int u = 0; u < 8; u++) {
                int row = u * 16 + warp;
                uint32_t h0, l0, h1, l1;
                split2n(xr[u].x, xr[u].y, h0, l0);
                split2n(xr[u].z, xr[u].w, h1, l1);
                uint32_t byte = (uint32_t)(SWZ256(row, (lane >> 1)) + (lane & 1) * 8);
                *(uint2*)(sd + AH_B + byte) = make_uint2(h0, h1);
                *(uint2*)(sd + AL_B + byte) = make_uint2(l0, l1);
            }
            asm volatile("cp.async.wait_group 0;" ::: "memory");
        }
        __syncthreads();
    }

    // ---- cross-kstep reduction into logits tile Ls[128][68] (÷32 unscale) ----
    float* Ls = (float*)dsm;
    for (int idx = tid; idx < TM * LS_STRIDE; idx += NTH) Ls[idx] = 0.f;
    __syncthreads();

    for (int round = 0; round < 2; round++) {
        if (ksw == round) {
            #pragma unroll
            for (int i = 0; i < 2; i++) {
                int rt = 32 * h2 + 16 * i + g;
                #pragma unroll
                for (int j = 0; j < 4; j++) {
                    int cc = 32 * e2 + 8 * j + 2 * tig;
                    Ls[rt * LS_STRIDE + cc]           += acc[i][j][0] * INV32;
                    Ls[rt * LS_STRIDE + cc + 1]       += acc[i][j][1] * INV32;
                    Ls[(rt + 8) * LS_STRIDE + cc]     += acc[i][j][2] * INV32;
                    Ls[(rt + 8) * LS_STRIDE + cc + 1] += acc[i][j][3] * INV32;
                }
            }
        }
        __syncthreads();
    }

    // ---- epilogue: per-token top-8 + softmax + load scatter ----
    if (tid < TM) {
        const int t = tid;
        size_t gt = (size_t)(t0 + t);

        float nzf[NE];
        const float4* nr = (const float4*)(noise + gt * NE);
        #pragma unroll
        for (int i = 0; i < 16; i++) {
            float4 v = nr[i];
            nzf[4 * i + 0] = v.x; nzf[4 * i + 1] = v.y;
            nzf[4 * i + 2] = v.z; nzf[4 * i + 3] = v.w;
        }

        float tv[TK];
        int   ti_[TK];
        #pragma unroll
        for (int k = 0; k < TK; k++) { tv[k] = -INFINITY; ti_[k] = -1; }

        for (int e = 0; e < NE; e++) {
            float v = Ls[t * LS_STRIDE + e] + 0.01f * nzf[e] - sBias[e];
            if (v > tv[TK - 1]) {                 // strict >: earlier equal value stays
                int p = TK - 1;
                while (p > 0 && tv[p - 1] < v) {  // stop at equal -> stable insert
                    tv[p] = tv[p - 1];
                    ti_[p] = ti_[p - 1];
                    --p;
                }
                tv[p] = v;
                ti_[p] = e;
            }
        }

        float m = tv[0];
        float w[TK];
        float ssum = 0.f;
        #pragma unroll
        for (int k = 0; k < TK; k++) { w[k] = expf(tv[k] - m); ssum += w[k]; }
        float inv = 1.0f / ssum;

        size_t woff = (size_t)ntok * TK;
        #pragma unroll
        for (int k = 0; k < TK; k++) {
            float wk = w[k] * inv;
            out[gt * TK + k]        = (float)ti_[k];
            out[woff + gt * TK + k] = wk;
            atomicAdd(&sLoads[ti_[k]], wk);
        }
    }
    __syncthreads();
    if (tid < NE) atomicAdd(&g_acc[tid], sLoads[tid]);

    // ---- fused finalize: last CTA writes EMA + bias strength ----
    __threadfence();
    __syncthreads();
    if (tid == 0) {
        unsigned int n = atomicAdd(&g_done, 1u);
        sLast = (n == gridDim.x - 1) ? 1 : 0;
    }
    __syncthreads();
    if (sLast && tid < NE) {
        float batch = atomicAdd(&g_acc[tid], 0.0f) / (float)ntok;
        size_t bofs = (size_t)ntok * TK * 2;
        out[bofs + tid] = 0.999f * loads[tid] + (1.0f - 0.999f) * batch;
        if (tid == 0) { out[bofs + NE] = g_nbs; g_done = 0u; }
    }
}

// ---------------------------------------------------------------------------
// Launch
// ---------------------------------------------------------------------------
extern "C" void kernel_launch(void* const* d_in, const int* in_sizes, int n_in,
                              void* d_out, int out_size)
{
    const float* X     = (const float*)d_in[0];  // hidden_states [4,4096,2048]
    const float* W     = (const float*)d_in[1];  // router_w [64,2048]
    const float* loads = (const float*)d_in[2];  // expert_loads [64]
    const float* bs    = (const float*)d_in[3];  // bias_strength [1]
    const float* noise = (const float*)d_in[4];  // noise [16384,64]
    float* out = (float*)d_out;

    int ntok = in_sizes[0] / DIM;

    cudaFuncSetAttribute(k_router, cudaFuncAttributeMaxDynamicSharedMemorySize, DYN_BYTES);

    k_setup<<<NE + 1, 256>>>(W, loads, bs);
    k_router<<<ntok / TM, NTH, DYN_BYTES>>>(X, noise, loads, out, ntok);
}

// round 16
// speedup vs baseline: 1.6001x; 1.1165x over previous
#include <cuda_runtime.h>
#include <cuda_fp16.h>
#include <math.h>
#include <stdint.h>

#define NE   64
#define TK   8
#define DIM  2048
#define TM   64             // tokens per CTA
#define KC   64             // fp32 k per chunk (64 fp16 = 128B row)
#define NCH  (DIM / KC)     // 32 chunks
#define NTH  256
#define INV2048 (1.0f / 2048.0f)
#define LS_STRIDE 68

// stage byte layout: 128B rows, XOR-swizzled 16B chunks
#define AH_B 0
#define AL_B 8192
#define BH_B 16384
#define BL_B 24576
#define STG_B 32768
#define DYN_BYTES (2 * STG_B)    // 65536

__device__ __align__(16) uint16_t g_wh16[NE * DIM];   // W hi (fp16)
__device__ __align__(16) uint16_t g_wl16[NE * DIM];   // W lo (fp16, scaled 2^11)
__device__ __align__(16) float g_bias[NE];
__device__ float g_nbs;
__device__ float g_acc[NE];
__device__ unsigned int g_done;   // zero-init; reset by last CTA each run

// swizzled byte offset of 16B chunk (row, c 0..7) within a plane (128B rows)
#define SWZ(row, c) (((row) << 7) + ((((c) ^ ((row) & 7))) << 4))

// 2-term fp16 split of (x,y) -> packed hi fp16x2, lo fp16x2 (lo scaled 2^11)
static __device__ __forceinline__ void split2(float x, float y,
                                              uint32_t& hh, uint32_t& ll)
{
    __half2 a = __floats2half2_rn(x, y);
    float rx = (x - __half2float(__low2half(a))) * 2048.f;
    float ry = (y - __half2float(__high2half(a))) * 2048.f;
    __half2 l = __floats2half2_rn(rx, ry);
    hh = *(uint32_t*)&a;
    ll = *(uint32_t*)&l;
}

static __device__ __forceinline__ void mma16f(float* c,
    uint32_t a0, uint32_t a1, uint32_t a2, uint32_t a3, uint32_t b0, uint32_t b1)
{
    asm volatile(
        "mma.sync.aligned.m16n8k16.row.col.f32.f16.f16.f32 "
        "{%0,%1,%2,%3}, {%4,%5,%6,%7}, {%8,%9}, {%0,%1,%2,%3};"
        : "+f"(c[0]), "+f"(c[1]), "+f"(c[2]), "+f"(c[3])
        : "r"(a0), "r"(a1), "r"(a2), "r"(a3), "r"(b0), "r"(b1));
}

static __device__ __forceinline__ void ldsm4(uint32_t& r0, uint32_t& r1,
                                             uint32_t& r2, uint32_t& r3, uint32_t a)
{
    asm volatile("ldmatrix.sync.aligned.m8n8.x4.shared.b16 {%0,%1,%2,%3}, [%4];"
                 : "=r"(r0), "=r"(r1), "=r"(r2), "=r"(r3) : "r"(a));
}

static __device__ __forceinline__ void cpa16(uint32_t dst, const void* src) {
    asm volatile("cp.async.ca.shared.global [%0], [%1], 16;"
                 :: "r"(dst), "l"(src) : "memory");
}

// ---------------------------------------------------------------------------
// Setup: split W into fp16 hi/lo planes (blocks 0..63), bias (block 64)
// ---------------------------------------------------------------------------
__global__ void k_setup(const float* __restrict__ W,
                        const float* __restrict__ loads,
                        const float* __restrict__ bs)
{
    int b = blockIdx.x, tid = threadIdx.x;

    if (b < NE) {
        const float2* wr = (const float2*)(W + (size_t)b * DIM);
        uint32_t* wh = (uint32_t*)g_wh16;
        uint32_t* wl = (uint32_t*)g_wl16;
        #pragma unroll
        for (int u = 0; u < 4; u++) {
            int f = u * 256 + tid;
            float2 v = wr[f];
            uint32_t hh, ll;
            split2(v.x, v.y, hh, ll);
            int idx = b * (DIM / 2) + f;
            wh[idx] = hh;
            wl[idx] = ll;
        }
    } else {
        __shared__ float s[NE], s2[NE];
        if (tid < NE) s[tid] = loads[tid];
        __syncthreads();
        float sum = 0.f, q = 0.f;
        const float t = 1.0f / (float)NE;
        if (tid < NE) {
            #pragma unroll
            for (int i = 0; i < NE; i++) sum += s[i];
            sum = fmaxf(sum, 1e-8f);
            q = s[tid] / sum;
            s2[tid] = t * (logf(t) - logf(fmaxf(q, 1e-8f)));
        }
        __syncthreads();
        if (tid < NE) {
            float kl = 0.f;
            #pragma unroll
            for (int i = 0; i < NE; i++) kl += s2[i];
            float adaptive = 1.0f / (1.0f + expf(-10.0f * kl));
            float nbs = 0.9f * bs[0] + 0.1f * adaptive;
            g_bias[tid] = tanhf((q - t) * (float)NE) * nbs;
            g_acc[tid] = 0.f;
            if (tid == 0) g_nbs = nbs;
        }
    }
}

// ---------------------------------------------------------------------------
// Router: fp16 2-term / 3-product mma16 GEMM, TM=64, 2 independent CTAs/SM
// warp w (0..7): h = w&1 token half, e2 = (w>>1)&1 expert half, ksw = w>>2
// ---------------------------------------------------------------------------
__global__ __launch_bounds__(NTH, 2) void k_router(
    const float* __restrict__ X,      // [ntok, DIM]
    const float* __restrict__ noise,  // [ntok, NE]
    const float* __restrict__ loads,  // [NE]
    float* __restrict__ out,
    int ntok)
{
    extern __shared__ __align__(16) char dsm[];
    __shared__ float sLoads[NE];
    __shared__ float sBias[NE];
    __shared__ int sLast;

    const int tid  = threadIdx.x;
    const int lane = tid & 31;
    const int warp = tid >> 5;
    const int h    = warp & 1;        // token half (32 tokens, 2 M-tiles)
    const int e2   = (warp >> 1) & 1; // expert half
    const int ksw  = warp >> 2;       // k32 half of chunk (2 k16 steps)
    const int g    = lane >> 2;
    const int tig  = lane & 3;
    const int t0   = blockIdx.x * TM;

    if (tid < NE) { sLoads[tid] = 0.f; sBias[tid] = g_bias[tid]; }

    const uint32_t smem32 = (uint32_t)__cvta_generic_to_shared(dsm);

    // ldsm lane decomposition
    const int laneA15 = lane & 15;
    const int kaSel = lane >> 4;           // A chunk select
    const int kbSel = (lane >> 3) & 1;     // B chunk select
    const int rowBbase = 32 * e2 + ((lane >> 4) << 3) + (lane & 7);

    // X fill: flat float4 f = u*256+tid -> row = u*16 + (tid>>4), c4 = tid&15
    const int frow0 = tid >> 4;      // 0..15
    const int fc4   = tid & 15;
    // B fill: f = u*256+tid -> row = f>>3, chunk = f&7 (u<2)

    float acc0[2][4][4], accS[2][4][4];
    #pragma unroll
    for (int i = 0; i < 2; i++)
        #pragma unroll
        for (int j = 0; j < 4; j++)
            #pragma unroll
            for (int q = 0; q < 4; q++) { acc0[i][j][q] = 0.f; accS[i][j][q] = 0.f; }

    float4 xr[4];

    // ---- fill chunk 0 into stage 0 ----
    {
        #pragma unroll
        for (int u = 0; u < 4; u++) {
            int row = u * 16 + frow0;
            xr[u] = *(const float4*)(X + (size_t)(t0 + row) * DIM + fc4 * 4);
        }
        #pragma unroll
        for (int u = 0; u < 4; u++) {
            int row = u * 16 + frow0;
            uint32_t h0, l0, h1, l1;
            split2(xr[u].x, xr[u].y, h0, l0);
            split2(xr[u].z, xr[u].w, h1, l1);
            uint32_t byte = (uint32_t)(SWZ(row, (fc4 >> 1)) + (fc4 & 1) * 8);
            *(uint2*)(dsm + AH_B + byte) = make_uint2(h0, h1);
            *(uint2*)(dsm + AL_B + byte) = make_uint2(l0, l1);
        }
        #pragma unroll
        for (int u = 0; u < 2; u++) {
            int f = u * 256 + tid;
            int row = f >> 3, cc = f & 7;
            uint32_t dst = smem32 + (uint32_t)SWZ(row, cc);
            cpa16(dst + BH_B, g_wh16 + (size_t)row * DIM + cc * 8);
            cpa16(dst + BL_B, g_wl16 + (size_t)row * DIM + cc * 8);
        }
        asm volatile("cp.async.commit_group;" ::: "memory");
        asm volatile("cp.async.wait_group 0;" ::: "memory");
    }
    __syncthreads();

    // ---- mainloop ----
    for (int c = 0; c < NCH; ++c) {
        const bool more = (c + 1 < NCH);
        if (more) {
            int kb = (c + 1) * KC;
            #pragma unroll
            for (int u = 0; u < 4; u++) {
                int row = u * 16 + frow0;
                xr[u] = *(const float4*)(X + (size_t)(t0 + row) * DIM + kb + fc4 * 4);
            }
            uint32_t sb = smem32 + (uint32_t)(((c + 1) & 1) * STG_B);
            #pragma unroll
            for (int u = 0; u < 2; u++) {
                int f = u * 256 + tid;
                int row = f >> 3, cc = f & 7;
                uint32_t dst = sb + (uint32_t)SWZ(row, cc);
                cpa16(dst + BH_B, g_wh16 + (size_t)row * DIM + kb + cc * 8);
                cpa16(dst + BL_B, g_wl16 + (size_t)row * DIM + kb + cc * 8);
            }
            asm volatile("cp.async.commit_group;" ::: "memory");
        }

        // ---- consume stage c&1 (conflict-free swizzled ldmatrix) ----
        {
            const uint32_t stg32 = smem32 + (uint32_t)((c & 1) * STG_B);

            #pragma unroll
            for (int kk = 0; kk < 2; kk++) {
                const int kstep = ksw * 2 + kk;

                uint32_t Ah[2][4], Al[2][4];
                #pragma unroll
                for (int i = 0; i < 2; i++) {
                    int rowA = 32 * h + 16 * i + laneA15;
                    int kc = kstep * 2 + kaSel;
                    uint32_t a = stg32 + (uint32_t)SWZ(rowA, kc);
                    ldsm4(Ah[i][0], Ah[i][1], Ah[i][2], Ah[i][3], a + AH_B);
                    ldsm4(Al[i][0], Al[i][1], Al[i][2], Al[i][3], a + AL_B);
                }
                #pragma unroll
                for (int jp = 0; jp < 2; jp++) {
                    int rowBj = rowBbase + 16 * jp;
                    int kc = kstep * 2 + kbSel;
                    uint32_t b = stg32 + (uint32_t)SWZ(rowBj, kc);
                    uint32_t Bh0, Bh1, Bh2, Bh3, Bl0, Bl1, Bl2, Bl3;
                    ldsm4(Bh0, Bh1, Bh2, Bh3, b + BH_B);
                    ldsm4(Bl0, Bl1, Bl2, Bl3, b + BL_B);
                    #pragma unroll
                    for (int i = 0; i < 2; i++) {
                        mma16f(acc0[i][2*jp],   Ah[i][0], Ah[i][1], Ah[i][2], Ah[i][3], Bh0, Bh1);
                        mma16f(accS[i][2*jp],   Ah[i][0], Ah[i][1], Ah[i][2], Ah[i][3], Bl0, Bl1);
                        mma16f(accS[i][2*jp],   Al[i][0], Al[i][1], Al[i][2], Al[i][3], Bh0, Bh1);
                        mma16f(acc0[i][2*jp+1], Ah[i][0], Ah[i][1], Ah[i][2], Ah[i][3], Bh2, Bh3);
                        mma16f(accS[i][2*jp+1], Ah[i][0], Ah[i][1], Ah[i][2], Ah[i][3], Bl2, Bl3);
                        mma16f(accS[i][2*jp+1], Al[i][0], Al[i][1], Al[i][2], Al[i][3], Bh2, Bh3);
                    }
                }
            }
        }

        // ---- store X(c+1) + drain B cp.async ----
        if (more) {
            char* sd = dsm + ((c + 1) & 1) * STG_B;
            #pragma unroll
            for (int u = 0; u < 4; u++) {
                int row = u * 16 + frow0;
                uint32_t h0, l0, h1, l1;
                split2(xr[u].x, xr[u].y, h0, l0);
                split2(xr[u].z, xr[u].w, h1, l1);
                uint32_t byte = (uint32_t)(SWZ(row, (fc4 >> 1)) + (fc4 & 1) * 8);
                *(uint2*)(sd + AH_B + byte) = make_uint2(h0, h1);
                *(uint2*)(sd + AL_B + byte) = make_uint2(l0, l1);
            }
            asm volatile("cp.async.wait_group 0;" ::: "memory");
        }
        __syncthreads();
    }

    // ---- cross-kstep reduction into logits tile Ls[64][68] ----
    float* Ls = (float*)dsm;
    for (int idx = tid; idx < TM * LS_STRIDE; idx += NTH) Ls[idx] = 0.f;
    __syncthreads();

    for (int round = 0; round < 2; round++) {
        if (ksw == round) {
            #pragma unroll
            for (int i = 0; i < 2; i++) {
                int rt = 32 * h + 16 * i + g;
                #pragma unroll
                for (int j = 0; j < 4; j++) {
                    int cc = 32 * e2 + 8 * j + 2 * tig;
                    Ls[rt * LS_STRIDE + cc]           += acc0[i][j][0] + accS[i][j][0] * INV2048;
                    Ls[rt * LS_STRIDE + cc + 1]       += acc0[i][j][1] + accS[i][j][1] * INV2048;
                    Ls[(rt + 8) * LS_STRIDE + cc]     += acc0[i][j][2] + accS[i][j][2] * INV2048;
                    Ls[(rt + 8) * LS_STRIDE + cc + 1] += acc0[i][j][3] + accS[i][j][3] * INV2048;
                }
            }
        }
        __syncthreads();
    }

    // ---- epilogue: per-token top-8 + softmax + load scatter ----
    if (tid < TM) {
        const int t = tid;
        size_t gt = (size_t)(t0 + t);

        float nzf[NE];
        const float4* nr = (const float4*)(noise + gt * NE);
        #pragma unroll
        for (int i = 0; i < 16; i++) {
            float4 v = nr[i];
            nzf[4 * i + 0] = v.x; nzf[4 * i + 1] = v.y;
            nzf[4 * i + 2] = v.z; nzf[4 * i + 3] = v.w;
        }

        float tv[TK];
        int   ti_[TK];
        #pragma unroll
        for (int k = 0; k < TK; k++) { tv[k] = -INFINITY; ti_[k] = -1; }

        for (int e = 0; e < NE; e++) {
            float v = Ls[t * LS_STRIDE + e] + 0.01f * nzf[e] - sBias[e];
            if (v > tv[TK - 1]) {                 // strict >: earlier equal value stays
                int p = TK - 1;
                while (p > 0 && tv[p - 1] < v) {  // stop at equal -> stable insert
                    tv[p] = tv[p - 1];
                    ti_[p] = ti_[p - 1];
                    --p;
                }
                tv[p] = v;
                ti_[p] = e;
            }
        }

        float m = tv[0];
        float w[TK];
        float ssum = 0.f;
        #pragma unroll
        for (int k = 0; k < TK; k++) { w[k] = expf(tv[k] - m); ssum += w[k]; }
        float inv = 1.0f / ssum;

        size_t woff = (size_t)ntok * TK;
        #pragma unroll
        for (int k = 0; k < TK; k++) {
            float wk = w[k] * inv;
            out[gt * TK + k]        = (float)ti_[k];
            out[woff + gt * TK + k] = wk;
            atomicAdd(&sLoads[ti_[k]], wk);
        }
    }
    __syncthreads();
    if (tid < NE) atomicAdd(&g_acc[tid], sLoads[tid]);

    // ---- fused finalize: last CTA writes EMA + bias strength ----
    __threadfence();
    __syncthreads();
    if (tid == 0) {
        unsigned int n = atomicAdd(&g_done, 1u);
        sLast = (n == gridDim.x - 1) ? 1 : 0;
    }
    __syncthreads();
    if (sLast && tid < NE) {
        float batch = atomicAdd(&g_acc[tid], 0.0f) / (float)ntok;
        size_t bofs = (size_t)ntok * TK * 2;
        out[bofs + tid] = 0.999f * loads[tid] + (1.0f - 0.999f) * batch;
        if (tid == 0) { out[bofs + NE] = g_nbs; g_done = 0u; }
    }
}

// ---------------------------------------------------------------------------
// Launch
// ---------------------------------------------------------------------------
extern "C" void kernel_launch(void* const* d_in, const int* in_sizes, int n_in,
                              void* d_out, int out_size)
{
    const float* X     = (const float*)d_in[0];  // hidden_states [4,4096,2048]
    const float* W     = (const float*)d_in[1];  // router_w [64,2048]
    const float* loads = (const float*)d_in[2];  // expert_loads [64]
    const float* bs    = (const float*)d_in[3];  // bias_strength [1]
    const float* noise = (const float*)d_in[4];  // noise [16384,64]
    float* out = (float*)d_out;

    int ntok = in_sizes[0] / DIM;

    cudaFuncSetAttribute(k_router, cudaFuncAttributeMaxDynamicSharedMemorySize, DYN_BYTES);

    k_setup<<<NE + 1, 256>>>(W, loads, bs);
    k_router<<<ntok / TM, NTH, DYN_BYTES>>>(X, noise, loads, out, ntok);
}

// round 17
// speedup vs baseline: 1.6401x; 1.0250x over previous
#include <cuda_runtime.h>
#include <cuda_fp16.h>
#include <math.h>
#include <stdint.h>

#define NE   64
#define TK   8
#define DIM  2048
#define TM   128            // tokens per CTA
#define KC   64             // fp32 k per chunk (64 fp16 = 128B row)
#define NCH  (DIM / KC)     // 32 chunks
#define NTH  512
#define INV2048 (1.0f / 2048.0f)
#define LS_STRIDE 68

// stage byte layout: 128B rows, XOR-swizzled 16B chunks
#define AH_B 0
#define AL_B 16384
#define BH_B 32768
#define BL_B 40960
#define STG_B 49152
#define DYN_BYTES (2 * STG_B)    // 98304

__device__ __align__(16) uint16_t g_wh16[NE * DIM];   // W hi (fp16)
__device__ __align__(16) uint16_t g_wl16[NE * DIM];   // W lo (fp16, scaled 2^11)
__device__ __align__(16) float g_bias[NE];
__device__ float g_nbs;
__device__ float g_acc[NE];
__device__ unsigned int g_done;   // zero-init; reset by last CTA each run

// swizzled byte offset of 16B chunk (row, c) within a plane
#define SWZ(row, c) (((row) << 7) + ((((c) ^ ((row) & 7))) << 4))

// 2-term fp16 split of (x,y) -> packed hi fp16x2, lo fp16x2 (lo scaled 2^11)
static __device__ __forceinline__ void split2(float x, float y,
                                              uint32_t& hh, uint32_t& ll)
{
    __half2 a = __floats2half2_rn(x, y);
    float rx = (x - __half2float(__low2half(a))) * 2048.f;
    float ry = (y - __half2float(__high2half(a))) * 2048.f;
    __half2 l = __floats2half2_rn(rx, ry);
    hh = *(uint32_t*)&a;
    ll = *(uint32_t*)&l;
}

static __device__ __forceinline__ void mma16f(float* c,
    uint32_t a0, uint32_t a1, uint32_t a2, uint32_t a3, uint32_t b0, uint32_t b1)
{
    asm volatile(
        "mma.sync.aligned.m16n8k16.row.col.f32.f16.f16.f32 "
        "{%0,%1,%2,%3}, {%4,%5,%6,%7}, {%8,%9}, {%0,%1,%2,%3};"
        : "+f"(c[0]), "+f"(c[1]), "+f"(c[2]), "+f"(c[3])
        : "r"(a0), "r"(a1), "r"(a2), "r"(a3), "r"(b0), "r"(b1));
}

static __device__ __forceinline__ void ldsm4(uint32_t& r0, uint32_t& r1,
                                             uint32_t& r2, uint32_t& r3, uint32_t a)
{
    asm volatile("ldmatrix.sync.aligned.m8n8.x4.shared.b16 {%0,%1,%2,%3}, [%4];"
                 : "=r"(r0), "=r"(r1), "=r"(r2), "=r"(r3) : "r"(a));
}

static __device__ __forceinline__ void cpa16(uint32_t dst, const void* src) {
    asm volatile("cp.async.ca.shared.global [%0], [%1], 16;"
                 :: "r"(dst), "l"(src) : "memory");
}

// ---------------------------------------------------------------------------
// Setup: split W into fp16 hi/lo planes (blocks 0..63), bias (block 64)
// ---------------------------------------------------------------------------
__global__ void k_setup(const float* __restrict__ W,
                        const float* __restrict__ loads,
                        const float* __restrict__ bs)
{
    int b = blockIdx.x, tid = threadIdx.x;

    if (b < NE) {
        const float2* wr = (const float2*)(W + (size_t)b * DIM);
        uint32_t* wh = (uint32_t*)g_wh16;
        uint32_t* wl = (uint32_t*)g_wl16;
        #pragma unroll
        for (int u = 0; u < 4; u++) {
            int f = u * 256 + tid;
            float2 v = wr[f];
            uint32_t hh, ll;
            split2(v.x, v.y, hh, ll);
            int idx = b * (DIM / 2) + f;
            wh[idx] = hh;
            wl[idx] = ll;
        }
    } else {
        __shared__ float s[NE], s2[NE];
        if (tid < NE) s[tid] = loads[tid];
        __syncthreads();
        float sum = 0.f, q = 0.f;
        const float t = 1.0f / (float)NE;
        if (tid < NE) {
            #pragma unroll
            for (int i = 0; i < NE; i++) sum += s[i];
            sum = fmaxf(sum, 1e-8f);
            q = s[tid] / sum;
            s2[tid] = t * (logf(t) - logf(fmaxf(q, 1e-8f)));
        }
        __syncthreads();
        if (tid < NE) {
            float kl = 0.f;
            #pragma unroll
            for (int i = 0; i < NE; i++) kl += s2[i];
            float adaptive = 1.0f / (1.0f + expf(-10.0f * kl));
            float nbs = 0.9f * bs[0] + 0.1f * adaptive;
            g_bias[tid] = tanhf((q - t) * (float)NE) * nbs;
            g_acc[tid] = 0.f;
            if (tid == 0) g_nbs = nbs;
        }
    }
}

// ---------------------------------------------------------------------------
// Router: fp16 2-term / 3-product mma16 GEMM, swizzled staging, 16 warps
// warp w (0..15): h2 = w&3 token quarter, e2 = (w>>2)&1 expert half, ksw = w>>3
// MMAs in 3 passes per k16-step (all-distinct accumulators within a pass).
// ---------------------------------------------------------------------------
__global__ __launch_bounds__(NTH, 1) void k_router(
    const float* __restrict__ X,      // [ntok, DIM]
    const float* __restrict__ noise,  // [ntok, NE]
    const float* __restrict__ loads,  // [NE]
    float* __restrict__ out,
    int ntok)
{
    extern __shared__ __align__(16) char dsm[];
    __shared__ float sLoads[NE];
    __shared__ float sBias[NE];
    __shared__ int sLast;

    const int tid  = threadIdx.x;
    const int lane = tid & 31;
    const int warp = tid >> 5;
    const int h2   = warp & 3;        // token quarter (32 tokens)
    const int e2   = (warp >> 2) & 1; // expert half
    const int ksw  = warp >> 3;       // k32 half of chunk
    const int g    = lane >> 2;
    const int tig  = lane & 3;
    const int t0   = blockIdx.x * TM;

    if (tid < NE) { sLoads[tid] = 0.f; sBias[tid] = g_bias[tid]; }

    const uint32_t smem32 = (uint32_t)__cvta_generic_to_shared(dsm);

    // X fill coords: flat float4 f = u*512+tid -> row = f>>4, c4 = f&15
    const int frow0 = tid >> 4;      // 0..31, + u*32
    const int fc4   = tid & 15;
    // B fill coords: row = tid>>3, chunk = tid&7 (one pass covers 64x8)
    const int brow = tid >> 3;
    const int bcc  = tid & 7;

    // ldsm lane decomposition
    const int laneA15 = lane & 15;
    const int kaSel = lane >> 4;
    const int kbSel = (lane >> 3) & 1;
    const int rowBbase = 32 * e2 + ((lane >> 4) << 3) + (lane & 7);

    float acc0[2][4][4], accS[2][4][4];
    #pragma unroll
    for (int i = 0; i < 2; i++)
        #pragma unroll
        for (int j = 0; j < 4; j++)
            #pragma unroll
            for (int q = 0; q < 4; q++) { acc0[i][j][q] = 0.f; accS[i][j][q] = 0.f; }

    float4 xr[4];

    // ---- fill chunk 0 into stage 0 ----
    {
        #pragma unroll
        for (int u = 0; u < 4; u++) {
            int row = u * 32 + frow0;
            xr[u] = *(const float4*)(X + (size_t)(t0 + row) * DIM + fc4 * 4);
        }
        #pragma unroll
        for (int u = 0; u < 4; u++) {
            int row = u * 32 + frow0;
            uint32_t h0, l0, h1, l1;
            split2(xr[u].x, xr[u].y, h0, l0);
            split2(xr[u].z, xr[u].w, h1, l1);
            uint32_t byte = (uint32_t)(SWZ(row, (fc4 >> 1)) + (fc4 & 1) * 8);
            *(uint2*)(dsm + AH_B + byte) = make_uint2(h0, h1);
            *(uint2*)(dsm + AL_B + byte) = make_uint2(l0, l1);
        }
        {
            uint32_t dst = smem32 + (uint32_t)SWZ(brow, bcc);
            cpa16(dst + BH_B, g_wh16 + (size_t)brow * DIM + bcc * 8);
            cpa16(dst + BL_B, g_wl16 + (size_t)brow * DIM + bcc * 8);
        }
        asm volatile("cp.async.commit_group;" ::: "memory");
        asm volatile("cp.async.wait_group 0;" ::: "memory");
    }
    __syncthreads();

    // ---- mainloop ----
    for (int c = 0; c < NCH; ++c) {
        const bool more = (c + 1 < NCH);
        if (more) {
            int kb = (c + 1) * KC;
            #pragma unroll
            for (int u = 0; u < 4; u++) {
                int row = u * 32 + frow0;
                xr[u] = *(const float4*)(X + (size_t)(t0 + row) * DIM + kb + fc4 * 4);
            }
            uint32_t sb = smem32 + (uint32_t)(((c + 1) & 1) * STG_B);
            uint32_t dst = sb + (uint32_t)SWZ(brow, bcc);
            cpa16(dst + BH_B, g_wh16 + (size_t)brow * DIM + kb + bcc * 8);
            cpa16(dst + BL_B, g_wl16 + (size_t)brow * DIM + kb + bcc * 8);
            asm volatile("cp.async.commit_group;" ::: "memory");
        }

        // ---- consume stage c&1: load ALL frags, then 3 MMA passes ----
        {
            const uint32_t stg32 = smem32 + (uint32_t)((c & 1) * STG_B);

            #pragma unroll
            for (int kk = 0; kk < 2; kk++) {
                const int kstep = ksw * 2 + kk;

                uint32_t Ah[2][4], Al[2][4], Bh[2][4], Bl[2][4];
                #pragma unroll
                for (int i = 0; i < 2; i++) {
                    int rowA = 32 * h2 + 16 * i + laneA15;
                    int kc = kstep * 2 + kaSel;
                    uint32_t a = stg32 + (uint32_t)SWZ(rowA, kc);
                    ldsm4(Ah[i][0], Ah[i][1], Ah[i][2], Ah[i][3], a + AH_B);
                    ldsm4(Al[i][0], Al[i][1], Al[i][2], Al[i][3], a + AL_B);
                }
                #pragma unroll
                for (int jp = 0; jp < 2; jp++) {
                    int rowBj = rowBbase + 16 * jp;
                    int kc = kstep * 2 + kbSel;
                    uint32_t b = stg32 + (uint32_t)SWZ(rowBj, kc);
                    ldsm4(Bh[jp][0], Bh[jp][1], Bh[jp][2], Bh[jp][3], b + BH_B);
                    ldsm4(Bl[jp][0], Bl[jp][1], Bl[jp][2], Bl[jp][3], b + BL_B);
                }

                // pass 1: hi*hi -> acc0 (8 distinct accumulators)
                #pragma unroll
                for (int i = 0; i < 2; i++)
                    #pragma unroll
                    for (int jp = 0; jp < 2; jp++) {
                        mma16f(acc0[i][2*jp],   Ah[i][0], Ah[i][1], Ah[i][2], Ah[i][3], Bh[jp][0], Bh[jp][1]);
                        mma16f(acc0[i][2*jp+1], Ah[i][0], Ah[i][1], Ah[i][2], Ah[i][3], Bh[jp][2], Bh[jp][3]);
                    }
                // pass 2: hi*lo -> accS (8 distinct accumulators)
                #pragma unroll
                for (int i = 0; i < 2; i++)
                    #pragma unroll
                    for (int jp = 0; jp < 2; jp++) {
                        mma16f(accS[i][2*jp],   Ah[i][0], Ah[i][1], Ah[i][2], Ah[i][3], Bl[jp][0], Bl[jp][1]);
                        mma16f(accS[i][2*jp+1], Ah[i][0], Ah[i][1], Ah[i][2], Ah[i][3], Bl[jp][2], Bl[jp][3]);
                    }
                // pass 3: lo*hi -> accS (distance 8 from pass 2)
                #pragma unroll
                for (int i = 0; i < 2; i++)
                    #pragma unroll
                    for (int jp = 0; jp < 2; jp++) {
                        mma16f(accS[i][2*jp],   Al[i][0], Al[i][1], Al[i][2], Al[i][3], Bh[jp][0], Bh[jp][1]);
                        mma16f(accS[i][2*jp+1], Al[i][0], Al[i][1], Al[i][2], Al[i][3], Bh[jp][2], Bh[jp][3]);
                    }
            }
        }

        // ---- store X(c+1) + drain B cp.async ----
        if (more) {
            char* sd = dsm + ((c + 1) & 1) * STG_B;
            #pragma unroll
            for (int u = 0; u < 4; u++) {
                int row = u * 32 + frow0;
                uint32_t h0, l0, h1, l1;
                split2(xr[u].x, xr[u].y, h0, l0);
                split2(xr[u].z, xr[u].w, h1, l1);
                uint32_t byte = (uint32_t)(SWZ(row, (fc4 >> 1)) + (fc4 & 1) * 8);
                *(uint2*)(sd + AH_B + byte) = make_uint2(h0, h1);
                *(uint2*)(sd + AL_B + byte) = make_uint2(l0, l1);
            }
            asm volatile("cp.async.wait_group 0;" ::: "memory");
        }
        __syncthreads();
    }

    // ---- cross-kstep reduction into logits tile Ls[128][68] ----
    float* Ls = (float*)dsm;
    for (int idx = tid; idx < TM * LS_STRIDE; idx += NTH) Ls[idx] = 0.f;
    __syncthreads();

    for (int round = 0; round < 2; round++) {
        if (ksw == round) {
            #pragma unroll
            for (int i = 0; i < 2; i++) {
                int rt = 32 * h2 + 16 * i + g;
                #pragma unroll
                for (int j = 0; j < 4; j++) {
                    int cc = 32 * e2 + 8 * j + 2 * tig;
                    Ls[rt * LS_STRIDE + cc]           += acc0[i][j][0] + accS[i][j][0] * INV2048;
                    Ls[rt * LS_STRIDE + cc + 1]       += acc0[i][j][1] + accS[i][j][1] * INV2048;
                    Ls[(rt + 8) * LS_STRIDE + cc]     += acc0[i][j][2] + accS[i][j][2] * INV2048;
                    Ls[(rt + 8) * LS_STRIDE + cc + 1] += acc0[i][j][3] + accS[i][j][3] * INV2048;
                }
            }
        }
        __syncthreads();
    }

    // ---- epilogue: per-token top-8 + softmax + load scatter ----
    if (tid < TM) {
        const int t = tid;
        size_t gt = (size_t)(t0 + t);

        float nzf[NE];
        const float4* nr = (const float4*)(noise + gt * NE);
        #pragma unroll
        for (int i = 0; i < 16; i++) {
            float4 v = nr[i];
            nzf[4 * i + 0] = v.x; nzf[4 * i + 1] = v.y;
            nzf[4 * i + 2] = v.z; nzf[4 * i + 3] = v.w;
        }

        float tv[TK];
        int   ti_[TK];
        #pragma unroll
        for (int k = 0; k < TK; k++) { tv[k] = -INFINITY; ti_[k] = -1; }

        for (int e = 0; e < NE; e++) {
            float v = Ls[t * LS_STRIDE + e] + 0.01f * nzf[e] - sBias[e];
            if (v > tv[TK - 1]) {                 // strict >: earlier equal value stays
                int p = TK - 1;
                while (p > 0 && tv[p - 1] < v) {  // stop at equal -> stable insert
                    tv[p] = tv[p - 1];
                    ti_[p] = ti_[p - 1];
                    --p;
                }
                tv[p] = v;
                ti_[p] = e;
            }
        }

        float m = tv[0];
        float w[TK];
        float ssum = 0.f;
        #pragma unroll
        for (int k = 0; k < TK; k++) { w[k] = expf(tv[k] - m); ssum += w[k]; }
        float inv = 1.0f / ssum;

        size_t woff = (size_t)ntok * TK;
        #pragma unroll
        for (int k = 0; k < TK; k++) {
            float wk = w[k] * inv;
            out[gt * TK + k]        = (float)ti_[k];
            out[woff + gt * TK + k] = wk;
            atomicAdd(&sLoads[ti_[k]], wk);
        }
    }
    __syncthreads();
    if (tid < NE) atomicAdd(&g_acc[tid], sLoads[tid]);

    // ---- fused finalize: last CTA writes EMA + bias strength ----
    __threadfence();
    __syncthreads();
    if (tid == 0) {
        unsigned int n = atomicAdd(&g_done, 1u);
        sLast = (n == gridDim.x - 1) ? 1 : 0;
    }
    __syncthreads();
    if (sLast && tid < NE) {
        float batch = atomicAdd(&g_acc[tid], 0.0f) / (float)ntok;
        size_t bofs = (size_t)ntok * TK * 2;
        out[bofs + tid] = 0.999f * loads[tid] + (1.0f - 0.999f) * batch;
        if (tid == 0) { out[bofs + NE] = g_nbs; g_done = 0u; }
    }
}

// ---------------------------------------------------------------------------
// Launch
// ---------------------------------------------------------------------------
extern "C" void kernel_launch(void* const* d_in, const int* in_sizes, int n_in,
                              void* d_out, int out_size)
{
    const float* X     = (const float*)d_in[0];  // hidden_states [4,4096,2048]
    const float* W     = (const float*)d_in[1];  // router_w [64,2048]
    const float* loads = (const float*)d_in[2];  // expert_loads [64]
    const float* bs    = (const float*)d_in[3];  // bias_strength [1]
    const float* noise = (const float*)d_in[4];  // noise [16384,64]
    float* out = (float*)d_out;

    int ntok = in_sizes[0] / DIM;

    cudaFuncSetAttribute(k_router, cudaFuncAttributeMaxDynamicSharedMemorySize, DYN_BYTES);

    k_setup<<<NE + 1, 256>>>(W, loads, bs);
    k_router<<<ntok / TM, NTH, DYN_BYTES>>>(X, noise, loads, out, ntok);
}